// round 2
// baseline (speedup 1.0000x reference)
#include <cuda_runtime.h>

#define S_LEN 4096
#define D_DIM 1024
#define BATCH 4
#define TOK   (BATCH * S_LEN)   // 16384

// scratch for q, k, v projections (allocation-free rule -> __device__ global)
__device__ float g_qkv[(size_t)3 * TOK * D_DIM];

// ---------------------------------------------------------------------------
// Projection GEMM: out[z] = X @ W[z] + b[z], z in {q,k,v}
// 128x128 tile, K-chunks of 8, double buffered, 256 threads, 8x8 micro-tile
// ---------------------------------------------------------------------------
__global__ __launch_bounds__(256, 2)
void proj_kernel(const float* __restrict__ X,
                 const float* __restrict__ Wq, const float* __restrict__ bq,
                 const float* __restrict__ Wk, const float* __restrict__ bk,
                 const float* __restrict__ Wv, const float* __restrict__ bv)
{
    const int z = blockIdx.z;
    const float* W    = (z == 0) ? Wq : (z == 1) ? Wk : Wv;
    const float* bias = (z == 0) ? bq : (z == 1) ? bk : bv;
    float* out = g_qkv + (size_t)z * TOK * D_DIM;

    const int m0 = blockIdx.y * 128;
    const int n0 = blockIdx.x * 128;

    __shared__ float As[2][8][128];   // [buf][k][m]
    __shared__ float Bs[2][8][128];   // [buf][k][n]

    const int t    = threadIdx.x;
    const int arow = t >> 1;            // 0..127
    const int ac   = (t & 1) * 4;       // 0 or 4
    const int brow = t >> 5;            // 0..7
    const int bc   = (t & 31) * 4;      // 0..124
    const int tx   = t & 15;
    const int ty   = t >> 4;

    const float* Ap = X + (size_t)(m0 + arow) * D_DIM + ac;
    const float* Bp = W + (size_t)brow * D_DIM + n0 + bc;

    float acc[8][8];
#pragma unroll
    for (int i = 0; i < 8; ++i)
#pragma unroll
        for (int j = 0; j < 8; ++j) acc[i][j] = 0.f;

    // prologue: tile 0
    {
        float4 ra = *(const float4*)Ap;
        float4 rb = *(const float4*)Bp;
        As[0][ac + 0][arow] = ra.x;
        As[0][ac + 1][arow] = ra.y;
        As[0][ac + 2][arow] = ra.z;
        As[0][ac + 3][arow] = ra.w;
        *(float4*)&Bs[0][brow][bc] = rb;
    }
    __syncthreads();

    const int NT = D_DIM / 8;           // 128
    for (int kt = 0; kt < NT; ++kt) {
        const int buf = kt & 1;
        float4 na, nb;
        if (kt + 1 < NT) {
            na = *(const float4*)(Ap + (kt + 1) * 8);
            nb = *(const float4*)(Bp + (size_t)(kt + 1) * 8 * D_DIM);
        }
#pragma unroll
        for (int k = 0; k < 8; ++k) {
            float a[8], b[8];
            *(float4*)&a[0] = *(const float4*)&As[buf][k][ty * 4];
            *(float4*)&a[4] = *(const float4*)&As[buf][k][64 + ty * 4];
            *(float4*)&b[0] = *(const float4*)&Bs[buf][k][tx * 4];
            *(float4*)&b[4] = *(const float4*)&Bs[buf][k][64 + tx * 4];
#pragma unroll
            for (int i = 0; i < 8; ++i)
#pragma unroll
                for (int j = 0; j < 8; ++j)
                    acc[i][j] += a[i] * b[j];
        }
        if (kt + 1 < NT) {
            const int nbuf = buf ^ 1;
            As[nbuf][ac + 0][arow] = na.x;
            As[nbuf][ac + 1][arow] = na.y;
            As[nbuf][ac + 2][arow] = na.z;
            As[nbuf][ac + 3][arow] = na.w;
            *(float4*)&Bs[nbuf][brow][bc] = nb;
            __syncthreads();
        }
    }

    // epilogue: add bias, store
#pragma unroll
    for (int ii = 0; ii < 2; ++ii)
#pragma unroll
        for (int i = 0; i < 4; ++i) {
            const int row = m0 + ii * 64 + ty * 4 + i;
#pragma unroll
            for (int jj = 0; jj < 2; ++jj) {
                const int col = n0 + jj * 64 + tx * 4;
                float4 r;
                r.x = acc[ii * 4 + i][jj * 4 + 0] + bias[col + 0];
                r.y = acc[ii * 4 + i][jj * 4 + 1] + bias[col + 1];
                r.z = acc[ii * 4 + i][jj * 4 + 2] + bias[col + 2];
                r.w = acc[ii * 4 + i][jj * 4 + 3] + bias[col + 3];
                *(float4*)&out[(size_t)row * D_DIM + col] = r;
            }
        }
}

// ---------------------------------------------------------------------------
// Flash attention: M=32 queries/CTA, key chunks of 64, d staged in 128-chunks
// 512 threads. O accumulator register-resident (64 floats/thread).
// ---------------------------------------------------------------------------
#define KV_PITCH 132
#define PS_PITCH 66
#define SM_FLOATS (32 * 1024 + 64 * KV_PITCH + 32 * PS_PITCH + 32 + 32 + 32 + 64 + 64)

__global__ __launch_bounds__(512, 1)
void attn_kernel(float* __restrict__ out)
{
    extern __shared__ float sm[];
    float* Qs   = sm;                     // [32][1024]
    float* KVs  = Qs + 32 * 1024;         // [64][132]
    float* Ps   = KVs + 64 * KV_PITCH;    // [32][66]
    float* m_s  = Ps + 32 * PS_PITCH;     // [32]
    float* l_s  = m_s + 32;               // [32]
    float* al_s = l_s + 32;               // [32]
    float* redm = al_s + 32;              // [16][4]
    float* reds = redm + 64;              // [16][4]

    const int t     = threadIdx.x;
    const int b     = blockIdx.y;
    const int qbase = blockIdx.x * 32;

    const float* qg = g_qkv + (size_t)b * S_LEN * D_DIM + (size_t)qbase * D_DIM;
    const float* kg = g_qkv + (size_t)TOK * D_DIM     + (size_t)b * S_LEN * D_DIM;
    const float* vg = g_qkv + (size_t)2 * TOK * D_DIM + (size_t)b * S_LEN * D_DIM;

    // stage Q tile (32 x 1024)
#pragma unroll
    for (int i = 0; i < 16; ++i) {
        const int idx = t + i * 512;       // float4 index, 8192 total
        const int row = idx >> 8;
        const int c4  = idx & 255;
        *(float4*)&Qs[row * 1024 + c4 * 4] =
            *(const float4*)(qg + (size_t)row * D_DIM + c4 * 4);
    }
    if (t < 32) { m_s[t] = -1e30f; l_s[t] = 0.f; }

    const int c    = t & 63;     // key col within chunk (S phase)
    const int rq   = t >> 6;     // row group 0..7 (S phase: rows rq+8i)
    const int rp   = t >> 4;     // row 0..31 (PV phase)
    const int cg   = t & 15;     // col group (PV phase)
    const int lane = t & 31;
    const int w    = t >> 5;

    float o[64];
#pragma unroll
    for (int i = 0; i < 64; ++i) o[i] = 0.f;

    const int kcmax = (qbase + 31) >> 6;
    for (int kc = 0; kc <= kcmax; ++kc) {
        const int j0 = kc << 6;

        // ---- phase 1: S = Q K^T over full d=1024, staged 128 at a time ----
        float s[4] = {0.f, 0.f, 0.f, 0.f};
        for (int dc = 0; dc < 8; ++dc) {
            __syncthreads();   // prior KVs use complete
#pragma unroll
            for (int i = 0; i < 4; ++i) {
                const int idx = t + i * 512;   // 2048 float4
                const int row = idx >> 5;
                const int c4  = idx & 31;
                *(float4*)&KVs[row * KV_PITCH + c4 * 4] =
                    *(const float4*)(kg + (size_t)(j0 + row) * D_DIM + dc * 128 + c4 * 4);
            }
            __syncthreads();
            const float* Kr = &KVs[c * KV_PITCH];
            const float* Q0 = &Qs[(rq + 0)  * 1024 + dc * 128];
            const float* Q1 = &Qs[(rq + 8)  * 1024 + dc * 128];
            const float* Q2 = &Qs[(rq + 16) * 1024 + dc * 128];
            const float* Q3 = &Qs[(rq + 24) * 1024 + dc * 128];
#pragma unroll 4
            for (int d4 = 0; d4 < 32; ++d4) {
                const float4 kv = *(const float4*)(Kr + d4 * 4);
                float4 q;
                q = *(const float4*)(Q0 + d4 * 4);
                s[0] += q.x * kv.x + q.y * kv.y + q.z * kv.z + q.w * kv.w;
                q = *(const float4*)(Q1 + d4 * 4);
                s[1] += q.x * kv.x + q.y * kv.y + q.z * kv.z + q.w * kv.w;
                q = *(const float4*)(Q2 + d4 * 4);
                s[2] += q.x * kv.x + q.y * kv.y + q.z * kv.z + q.w * kv.w;
                q = *(const float4*)(Q3 + d4 * 4);
                s[3] += q.x * kv.x + q.y * kv.y + q.z * kv.z + q.w * kv.w;
            }
        }

        // ---- scale + causal mask ----
#pragma unroll
        for (int i2 = 0; i2 < 4; ++i2) {
            const int qr = qbase + rq + 8 * i2;
            s[i2] = ((j0 + c) <= qr) ? s[i2] * 0.03125f : -1e30f;
        }

        // ---- online softmax bookkeeping ----
        float mx[4] = {s[0], s[1], s[2], s[3]};
#pragma unroll
        for (int off = 16; off; off >>= 1) {
#pragma unroll
            for (int i2 = 0; i2 < 4; ++i2)
                mx[i2] = fmaxf(mx[i2], __shfl_xor_sync(0xffffffffu, mx[i2], off));
        }
        if (lane == 0) {
#pragma unroll
            for (int i2 = 0; i2 < 4; ++i2) redm[w * 4 + i2] = mx[i2];
        }
        __syncthreads();
        if (t < 32) {
            const int r  = t;
            const int rr = r & 7;
            const int ii = r >> 3;
            const float rowmax = fmaxf(redm[(2 * rr) * 4 + ii], redm[(2 * rr + 1) * 4 + ii]);
            const float mo = m_s[r];
            const float mn = fmaxf(mo, rowmax);
            m_s[r]  = mn;
            al_s[r] = __expf(mo - mn);
        }
        __syncthreads();

        float p[4], ps[4];
#pragma unroll
        for (int i2 = 0; i2 < 4; ++i2) {
            const int r = rq + 8 * i2;
            p[i2] = __expf(s[i2] - m_s[r]);   // masked s=-1e30 -> exp underflows to 0
            Ps[r * PS_PITCH + c] = p[i2];
            ps[i2] = p[i2];
        }
#pragma unroll
        for (int off = 16; off; off >>= 1) {
#pragma unroll
            for (int i2 = 0; i2 < 4; ++i2)
                ps[i2] += __shfl_xor_sync(0xffffffffu, ps[i2], off);
        }
        if (lane == 0) {
#pragma unroll
            for (int i2 = 0; i2 < 4; ++i2) reds[w * 4 + i2] = ps[i2];
        }
        __syncthreads();
        if (t < 32) {
            const int r  = t;
            const int rr = r & 7;
            const int ii = r >> 3;
            const float rsum = reds[(2 * rr) * 4 + ii] + reds[(2 * rr + 1) * 4 + ii];
            l_s[r] = l_s[r] * al_s[r] + rsum;
        }

        // ---- rescale O by alpha ----
        const float alpha = al_s[rp];
#pragma unroll
        for (int i = 0; i < 64; ++i) o[i] *= alpha;

        // ---- phase 2: O += P @ V, d staged 128 at a time ----
#pragma unroll
        for (int dc = 0; dc < 8; ++dc) {
            __syncthreads();   // prior KVs use complete (incl. reds read above)
#pragma unroll
            for (int i = 0; i < 4; ++i) {
                const int idx = t + i * 512;
                const int row = idx >> 5;
                const int c4  = idx & 31;
                *(float4*)&KVs[row * KV_PITCH + c4 * 4] =
                    *(const float4*)(vg + (size_t)(j0 + row) * D_DIM + dc * 128 + c4 * 4);
            }
            __syncthreads();
            const float* Pr = &Ps[rp * PS_PITCH];
#pragma unroll 2
            for (int j = 0; j < 64; ++j) {
                const float pv = Pr[j];
#pragma unroll
                for (int i2 = 0; i2 < 4; ++i2) {
                    const float2 vv = *(const float2*)&KVs[j * KV_PITCH + 32 * i2 + 2 * cg];
                    o[dc * 8 + 2 * i2 + 0] += pv * vv.x;
                    o[dc * 8 + 2 * i2 + 1] += pv * vv.y;
                }
            }
        }
    }

    // ---- epilogue: normalize and store ----
    const float inv = 1.0f / l_s[rp];
    float* og = out + (size_t)b * S_LEN * D_DIM + (size_t)(qbase + rp) * D_DIM;
#pragma unroll
    for (int dc = 0; dc < 8; ++dc)
#pragma unroll
        for (int i2 = 0; i2 < 4; ++i2) {
            float2 vv;
            vv.x = o[dc * 8 + 2 * i2 + 0] * inv;
            vv.y = o[dc * 8 + 2 * i2 + 1] * inv;
            *(float2*)&og[dc * 128 + 32 * i2 + 2 * cg] = vv;
        }
}

// ---------------------------------------------------------------------------
extern "C" void kernel_launch(void* const* d_in, const int* in_sizes, int n_in,
                              void* d_out, int out_size)
{
    const float* x  = (const float*)d_in[0];
    const float* Wq = (const float*)d_in[1];
    const float* bq = (const float*)d_in[2];
    const float* Wk = (const float*)d_in[3];
    const float* bk = (const float*)d_in[4];
    const float* Wv = (const float*)d_in[5];
    const float* bv = (const float*)d_in[6];
    float* out = (float*)d_out;

    dim3 pg(D_DIM / 128, TOK / 128, 3);
    proj_kernel<<<pg, 256>>>(x, Wq, bq, Wk, bk, Wv, bv);

    const size_t attn_smem = (size_t)SM_FLOATS * sizeof(float);   // 174208 B
    cudaFuncSetAttribute(attn_kernel, cudaFuncAttributeMaxDynamicSharedMemorySize,
                         (int)attn_smem);
    dim3 ag(S_LEN / 32, BATCH);
    attn_kernel<<<ag, 512, attn_smem>>>(out);
}

// round 4
// speedup vs baseline: 4.3482x; 4.3482x over previous
#include <cuda_runtime.h>
#include <cstdint>

#define S_LEN 4096
#define D_DIM 1024
#define BATCH 4
#define TOK   (BATCH * S_LEN)   // 16384

// scratch for q, k, v projections (tf32-rounded fp32)
__device__ float g_qkv[(size_t)3 * TOK * D_DIM];

// ---------------------------------------------------------------------------
// helpers
// ---------------------------------------------------------------------------
__device__ __forceinline__ float rna_tf32(float x) {
    uint32_t u;
    asm("cvt.rna.tf32.f32 %0, %1;" : "=r"(u) : "f"(x));
    return __uint_as_float(u);
}

__device__ __forceinline__ void mma_tf32(float* d,
                                         uint32_t a0, uint32_t a1, uint32_t a2, uint32_t a3,
                                         uint32_t b0, uint32_t b1) {
    asm volatile(
        "mma.sync.aligned.m16n8k8.row.col.f32.tf32.tf32.f32 "
        "{%0,%1,%2,%3}, {%4,%5,%6,%7}, {%8,%9}, {%0,%1,%2,%3};"
        : "+f"(d[0]), "+f"(d[1]), "+f"(d[2]), "+f"(d[3])
        : "r"(a0), "r"(a1), "r"(a2), "r"(a3), "r"(b0), "r"(b1));
}

// ---------------------------------------------------------------------------
// Projection GEMM (tf32 mma): out[z] = X @ W[z] + b[z]
// 128x128 tile, BK=16, double buffered, 256 threads (8 warps), warp = 32x64
// ---------------------------------------------------------------------------
#define XS_PITCH 20
#define WS_PITCH 136

__global__ __launch_bounds__(256, 2)
void proj_kernel(const float* __restrict__ X,
                 const float* __restrict__ Wq, const float* __restrict__ bq,
                 const float* __restrict__ Wk, const float* __restrict__ bk,
                 const float* __restrict__ Wv, const float* __restrict__ bv)
{
    const int z = blockIdx.z;
    const float* W    = (z == 0) ? Wq : (z == 1) ? Wk : Wv;
    const float* bias = (z == 0) ? bq : (z == 1) ? bk : bv;
    float* out = g_qkv + (size_t)z * TOK * D_DIM;

    const int m0 = blockIdx.y * 128;
    const int n0 = blockIdx.x * 128;

    __shared__ float Xs[2][128 * XS_PITCH];   // [m][k], pitch 20
    __shared__ float Ws[2][16 * WS_PITCH];    // [k][n], pitch 136

    const int t = threadIdx.x, w = t >> 5, lane = t & 31;
    const int wm = w >> 1, wn = w & 1;        // warp tile: m32 x n64
    const int l4 = lane >> 2, lm = lane & 3;

    float acc[16][4];                          // [mt*8+nt][4]
#pragma unroll
    for (int i = 0; i < 16; ++i)
#pragma unroll
        for (int j = 0; j < 4; ++j) acc[i][j] = 0.f;

    float4 xa[2], wa[2];
    // prologue: load + store tile 0
#pragma unroll
    for (int i = 0; i < 2; ++i) {
        const int idx = t + i * 256;                  // 0..511
        const int xr = idx >> 2, xq = idx & 3;
        xa[i] = *(const float4*)(X + (size_t)(m0 + xr) * D_DIM + xq * 4);
        const int wk = idx >> 5, nq = idx & 31;
        wa[i] = *(const float4*)(W + (size_t)wk * D_DIM + n0 + nq * 4);
    }
#pragma unroll
    for (int i = 0; i < 2; ++i) {
        const int idx = t + i * 256;
        const int xr = idx >> 2, xq = idx & 3;
        float* d = &Xs[0][xr * XS_PITCH + xq * 4];
        d[0] = rna_tf32(xa[i].x); d[1] = rna_tf32(xa[i].y);
        d[2] = rna_tf32(xa[i].z); d[3] = rna_tf32(xa[i].w);
        const int wk = idx >> 5, nq = idx & 31;
        float* d2 = &Ws[0][wk * WS_PITCH + nq * 4];
        d2[0] = rna_tf32(wa[i].x); d2[1] = rna_tf32(wa[i].y);
        d2[2] = rna_tf32(wa[i].z); d2[3] = rna_tf32(wa[i].w);
    }
    __syncthreads();

    for (int kt = 0; kt < 64; ++kt) {
        const int bf = kt & 1;
        if (kt < 63) {
#pragma unroll
            for (int i = 0; i < 2; ++i) {
                const int idx = t + i * 256;
                const int xr = idx >> 2, xq = idx & 3;
                xa[i] = *(const float4*)(X + (size_t)(m0 + xr) * D_DIM + (kt + 1) * 16 + xq * 4);
                const int wk = idx >> 5, nq = idx & 31;
                wa[i] = *(const float4*)(W + (size_t)((kt + 1) * 16 + wk) * D_DIM + n0 + nq * 4);
            }
        }
#pragma unroll
        for (int ks = 0; ks < 2; ++ks) {
            uint32_t a[2][4];
#pragma unroll
            for (int mt = 0; mt < 2; ++mt) {
                const float* Ar = &Xs[bf][(wm * 32 + mt * 16 + l4) * XS_PITCH + ks * 8 + lm];
                a[mt][0] = __float_as_uint(Ar[0]);
                a[mt][1] = __float_as_uint(Ar[8 * XS_PITCH]);
                a[mt][2] = __float_as_uint(Ar[4]);
                a[mt][3] = __float_as_uint(Ar[8 * XS_PITCH + 4]);
            }
            const float* Br = &Ws[bf][(ks * 8 + lm) * WS_PITCH + wn * 64 + l4];
#pragma unroll
            for (int nt = 0; nt < 8; ++nt) {
                const uint32_t b0 = __float_as_uint(Br[nt * 8]);
                const uint32_t b1 = __float_as_uint(Br[nt * 8 + 4 * WS_PITCH]);
                mma_tf32(acc[nt],     a[0][0], a[0][1], a[0][2], a[0][3], b0, b1);
                mma_tf32(acc[8 + nt], a[1][0], a[1][1], a[1][2], a[1][3], b0, b1);
            }
        }
        if (kt < 63) {
            const int nb = bf ^ 1;
#pragma unroll
            for (int i = 0; i < 2; ++i) {
                const int idx = t + i * 256;
                const int xr = idx >> 2, xq = idx & 3;
                float* d = &Xs[nb][xr * XS_PITCH + xq * 4];
                d[0] = rna_tf32(xa[i].x); d[1] = rna_tf32(xa[i].y);
                d[2] = rna_tf32(xa[i].z); d[3] = rna_tf32(xa[i].w);
                const int wk = idx >> 5, nq = idx & 31;
                float* d2 = &Ws[nb][wk * WS_PITCH + nq * 4];
                d2[0] = rna_tf32(wa[i].x); d2[1] = rna_tf32(wa[i].y);
                d2[2] = rna_tf32(wa[i].z); d2[3] = rna_tf32(wa[i].w);
            }
            __syncthreads();
        }
    }

    // epilogue: bias + round to tf32 (attention consumes these as mma operands)
#pragma unroll
    for (int mt = 0; mt < 2; ++mt) {
        const int r0 = m0 + wm * 32 + mt * 16 + l4;
#pragma unroll
        for (int nt = 0; nt < 8; ++nt) {
            const int cc = n0 + wn * 64 + nt * 8 + 2 * lm;
            const float bx = bias[cc], by = bias[cc + 1];
            float* a = acc[mt * 8 + nt];
            *(float2*)&out[(size_t)r0 * D_DIM + cc] =
                make_float2(rna_tf32(a[0] + bx), rna_tf32(a[1] + by));
            *(float2*)&out[(size_t)(r0 + 8) * D_DIM + cc] =
                make_float2(rna_tf32(a[2] + bx), rna_tf32(a[3] + by));
        }
    }
}

// ---------------------------------------------------------------------------
// Flash attention (tf32 mma): M=32 queries/CTA, 64-key chunks, d staged 128
// 256 threads (8 warps). S warp tile m16 x n16; PV warp tile m16 x n32.
// O accumulator register-resident (128 floats/thread).
// cp.async double-buffered KV staging.
// ---------------------------------------------------------------------------
#define QSP 1028
#define KVP 140
#define PSP 68
#define KVBUF (64 * KVP)
#define ATTN_SM_FLOATS (32 * QSP + 2 * KVBUF + 32 * PSP + 32 * 3 + 128 + 128)

__global__ __launch_bounds__(256, 1)
void attn_kernel(float* __restrict__ out)
{
    extern __shared__ float sm[];
    float* Qs   = sm;                      // [32][1028]
    float* KVs  = Qs + 32 * QSP;           // [2][64][140]
    float* Ps   = KVs + 2 * KVBUF;         // [32][68]
    float* m_s  = Ps + 32 * PSP;           // [32]
    float* l_s  = m_s + 32;
    float* al_s = l_s + 32;
    float* redm = al_s + 32;               // [32][4]
    float* reds = redm + 128;              // [32][4]

    const int t = threadIdx.x, w = t >> 5, lane = t & 31;
    const int wm = w >> 2, wn = w & 3;
    const int l4 = lane >> 2, lm = lane & 3;
    const int b = blockIdx.y;
    const int qtile = (int)gridDim.x - 1 - (int)blockIdx.x;  // heavy tiles first
    const int qbase = qtile * 32;

    const float* qg = g_qkv + (size_t)b * S_LEN * D_DIM + (size_t)qbase * D_DIM;
    const float* kg = g_qkv + (size_t)TOK * D_DIM     + (size_t)b * S_LEN * D_DIM;
    const float* vg = g_qkv + (size_t)2 * TOK * D_DIM + (size_t)b * S_LEN * D_DIM;

    const uint32_t kv_smem = (uint32_t)__cvta_generic_to_shared(KVs);

    // stage issuance: 64 rows x 128 floats into KVs[bf], one commit group
    auto issue = [&](const float* base, int j0, int dc, int bf) {
        const uint32_t dst = kv_smem + (uint32_t)bf * (KVBUF * 4);
        const float* src0 = base + (size_t)j0 * D_DIM + dc * 128;
#pragma unroll
        for (int i = 0; i < 8; ++i) {
            const int idx = t + i * 256;
            const int row = idx >> 5, q4 = idx & 31;
            asm volatile("cp.async.cg.shared.global [%0], [%1], 16;"
                         :: "r"(dst + (uint32_t)(row * KVP + q4 * 4) * 4),
                            "l"(src0 + (size_t)row * D_DIM + q4 * 4)
                         : "memory");
        }
        asm volatile("cp.async.commit_group;" ::: "memory");
    };

    issue(kg, 0, 0, 0);   // prefetch K chunk0 d-chunk0 while staging Q

    // stage Q tile (already tf32-rounded by proj)
#pragma unroll
    for (int i = 0; i < 32; ++i) {
        const int idx = t + i * 256;       // 8192 float4
        const int row = idx >> 8, c4 = idx & 255;
        *(float4*)&Qs[row * QSP + c4 * 4] =
            *(const float4*)(qg + (size_t)row * D_DIM + c4 * 4);
    }
    if (t < 32) { m_s[t] = -1e30f; l_s[t] = 0.f; }

    float oacc[128];
#pragma unroll
    for (int i = 0; i < 128; ++i) oacc[i] = 0.f;

    const int kcmax = (qbase + 31) >> 6;
    int bf = 0;

    for (int kc = 0; kc <= kcmax; ++kc) {
        const int j0 = kc << 6;
        float sacc[2][4] = {{0.f, 0.f, 0.f, 0.f}, {0.f, 0.f, 0.f, 0.f}};

        // ---- S = Q K^T, d staged in 8 chunks of 128 ----
        for (int dc = 0; dc < 8; ++dc) {
            __syncthreads();
            if (dc < 7) issue(kg, j0, dc + 1, bf ^ 1);
            else        issue(vg, j0, 0,      bf ^ 1);
            asm volatile("cp.async.wait_group 1;" ::: "memory");
            __syncthreads();
            const float* KB  = KVs + bf * KVBUF;
            const float* Qr0 = Qs + (wm * 16 + l4) * QSP + dc * 128;
            const float* Qr1 = Qr0 + 8 * QSP;
            const float* K0  = KB + (wn * 16 + l4) * KVP;
            const float* K1  = K0 + 8 * KVP;
#pragma unroll 2
            for (int ks = 0; ks < 16; ++ks) {
                const int c0 = ks * 8 + lm;
                const uint32_t a0 = __float_as_uint(Qr0[c0]);
                const uint32_t a1 = __float_as_uint(Qr1[c0]);
                const uint32_t a2 = __float_as_uint(Qr0[c0 + 4]);
                const uint32_t a3 = __float_as_uint(Qr1[c0 + 4]);
                const uint32_t b00 = __float_as_uint(K0[c0]);
                const uint32_t b01 = __float_as_uint(K0[c0 + 4]);
                const uint32_t b10 = __float_as_uint(K1[c0]);
                const uint32_t b11 = __float_as_uint(K1[c0 + 4]);
                mma_tf32(sacc[0], a0, a1, a2, a3, b00, b01);
                mma_tf32(sacc[1], a0, a1, a2, a3, b10, b11);
            }
            bf ^= 1;
        }

        // ---- scale + causal mask ----
        const int row0 = qbase + wm * 16 + l4;
#pragma unroll
        for (int t8 = 0; t8 < 2; ++t8) {
            const int cb = j0 + wn * 16 + t8 * 8 + 2 * lm;
            sacc[t8][0] = (cb     <= row0)     ? sacc[t8][0] * 0.03125f : -1e30f;
            sacc[t8][1] = (cb + 1 <= row0)     ? sacc[t8][1] * 0.03125f : -1e30f;
            sacc[t8][2] = (cb     <= row0 + 8) ? sacc[t8][2] * 0.03125f : -1e30f;
            sacc[t8][3] = (cb + 1 <= row0 + 8) ? sacc[t8][3] * 0.03125f : -1e30f;
        }

        // ---- online softmax ----
        float mx0 = fmaxf(fmaxf(sacc[0][0], sacc[0][1]), fmaxf(sacc[1][0], sacc[1][1]));
        float mx1 = fmaxf(fmaxf(sacc[0][2], sacc[0][3]), fmaxf(sacc[1][2], sacc[1][3]));
        mx0 = fmaxf(mx0, __shfl_xor_sync(0xffffffffu, mx0, 1));
        mx0 = fmaxf(mx0, __shfl_xor_sync(0xffffffffu, mx0, 2));
        mx1 = fmaxf(mx1, __shfl_xor_sync(0xffffffffu, mx1, 1));
        mx1 = fmaxf(mx1, __shfl_xor_sync(0xffffffffu, mx1, 2));
        if (lm == 0) {
            redm[(wm * 16 + l4) * 4 + wn]     = mx0;
            redm[(wm * 16 + l4 + 8) * 4 + wn] = mx1;
        }
        __syncthreads();
        if (t < 32) {
            const float rmx = fmaxf(fmaxf(redm[t * 4], redm[t * 4 + 1]),
                                    fmaxf(redm[t * 4 + 2], redm[t * 4 + 3]));
            const float mo = m_s[t], mn = fmaxf(mo, rmx);
            m_s[t]  = mn;
            al_s[t] = __expf(mo - mn);
        }
        __syncthreads();
        const float mrow0 = m_s[wm * 16 + l4];
        const float mrow1 = m_s[wm * 16 + l4 + 8];
        float ps0 = 0.f, ps1 = 0.f;
#pragma unroll
        for (int t8 = 0; t8 < 2; ++t8) {
            const float p0 = __expf(sacc[t8][0] - mrow0);
            const float p1 = __expf(sacc[t8][1] - mrow0);
            const float p2 = __expf(sacc[t8][2] - mrow1);
            const float p3 = __expf(sacc[t8][3] - mrow1);
            ps0 += p0 + p1;
            ps1 += p2 + p3;
            const int cc = wn * 16 + t8 * 8 + 2 * lm;
            *(float2*)&Ps[(wm * 16 + l4) * PSP + cc]     = make_float2(rna_tf32(p0), rna_tf32(p1));
            *(float2*)&Ps[(wm * 16 + l4 + 8) * PSP + cc] = make_float2(rna_tf32(p2), rna_tf32(p3));
        }
        ps0 += __shfl_xor_sync(0xffffffffu, ps0, 1);
        ps0 += __shfl_xor_sync(0xffffffffu, ps0, 2);
        ps1 += __shfl_xor_sync(0xffffffffu, ps1, 1);
        ps1 += __shfl_xor_sync(0xffffffffu, ps1, 2);
        if (lm == 0) {
            reds[(wm * 16 + l4) * 4 + wn]     = ps0;
            reds[(wm * 16 + l4 + 8) * 4 + wn] = ps1;
        }
        __syncthreads();
        if (t < 32) {
            l_s[t] = l_s[t] * al_s[t] +
                     (reds[t * 4] + reds[t * 4 + 1] + reds[t * 4 + 2] + reds[t * 4 + 3]);
        }

        // ---- rescale O ----
        const float alpha0 = al_s[wm * 16 + l4];
        const float alpha1 = al_s[wm * 16 + l4 + 8];
#pragma unroll
        for (int i = 0; i < 128; i += 4) {
            oacc[i]     *= alpha0;
            oacc[i + 1] *= alpha0;
            oacc[i + 2] *= alpha1;
            oacc[i + 3] *= alpha1;
        }

        // ---- O += P @ V, d staged in 8 chunks of 128 ----
#pragma unroll
        for (int dc = 0; dc < 8; ++dc) {
            __syncthreads();
            if (dc < 7) {
                issue(vg, j0, dc + 1, bf ^ 1);
                asm volatile("cp.async.wait_group 1;" ::: "memory");
            } else if (kc < kcmax) {
                issue(kg, j0 + 64, 0, bf ^ 1);
                asm volatile("cp.async.wait_group 1;" ::: "memory");
            } else {
                asm volatile("cp.async.wait_group 0;" ::: "memory");
            }
            __syncthreads();
            const float* VB  = KVs + bf * KVBUF;
            const float* Pr0 = Ps + (wm * 16 + l4) * PSP;
            const float* Pr1 = Pr0 + 8 * PSP;
#pragma unroll 1
            for (int ks = 0; ks < 8; ++ks) {
                const int kk = ks * 8 + lm;
                const uint32_t a0 = __float_as_uint(Pr0[kk]);
                const uint32_t a1 = __float_as_uint(Pr1[kk]);
                const uint32_t a2 = __float_as_uint(Pr0[kk + 4]);
                const uint32_t a3 = __float_as_uint(Pr1[kk + 4]);
                const float* V0 = VB + kk * KVP + wn * 32 + l4;
                const float* V4 = V0 + 4 * KVP;
#pragma unroll
                for (int nt = 0; nt < 4; ++nt) {
                    const uint32_t b0 = __float_as_uint(V0[nt * 8]);
                    const uint32_t b1 = __float_as_uint(V4[nt * 8]);
                    mma_tf32(&oacc[dc * 16 + nt * 4], a0, a1, a2, a3, b0, b1);
                }
            }
            bf ^= 1;
        }
    }

    // ---- epilogue: normalize, store ----
    const float inv0 = 1.0f / l_s[wm * 16 + l4];
    const float inv1 = 1.0f / l_s[wm * 16 + l4 + 8];
    float* og0 = out + (size_t)b * S_LEN * D_DIM + (size_t)(qbase + wm * 16 + l4) * D_DIM;
    float* og1 = og0 + 8 * D_DIM;
#pragma unroll
    for (int dc = 0; dc < 8; ++dc)
#pragma unroll
        for (int nt = 0; nt < 4; ++nt) {
            const int cc = dc * 128 + wn * 32 + nt * 8 + 2 * lm;
            const float* oa = &oacc[dc * 16 + nt * 4];
            *(float2*)&og0[cc] = make_float2(oa[0] * inv0, oa[1] * inv0);
            *(float2*)&og1[cc] = make_float2(oa[2] * inv1, oa[3] * inv1);
        }
}

// ---------------------------------------------------------------------------
extern "C" void kernel_launch(void* const* d_in, const int* in_sizes, int n_in,
                              void* d_out, int out_size)
{
    const float* x  = (const float*)d_in[0];
    const float* Wq = (const float*)d_in[1];
    const float* bq = (const float*)d_in[2];
    const float* Wk = (const float*)d_in[3];
    const float* bk = (const float*)d_in[4];
    const float* Wv = (const float*)d_in[5];
    const float* bv = (const float*)d_in[6];
    float* out = (float*)d_out;

    dim3 pg(D_DIM / 128, TOK / 128, 3);
    proj_kernel<<<pg, 256>>>(x, Wq, bq, Wk, bk, Wv, bv);

    const size_t attn_smem = (size_t)ATTN_SM_FLOATS * sizeof(float);   // 213376 B
    cudaFuncSetAttribute(attn_kernel, cudaFuncAttributeMaxDynamicSharedMemorySize,
                         (int)attn_smem);
    dim3 ag(S_LEN / 32, BATCH);
    attn_kernel<<<ag, 256, attn_smem>>>(out);
}